// round 15
// baseline (speedup 1.0000x reference)
#include <cuda_runtime.h>
#include <cuda_bf16.h>
#include <cstdint>

// ---------------------------------------------------------------------------
// SEE block on GB300 — split architecture, 2 launches.
// k_gemm1: bf16 mma.sync, BM=128 BN=128, ldmatrix frags, 2-step A prefetch /
//          1-step B prefetch (B staged from fp32 pw_w, L2-hot); first 64
//          blocks fold a tiled transpose of lin_w. y stored bf16.
// k_lif  : depthwise conv+BN+LIF1 -> masks in smem -> sparse linear+BN+LIF2
//          +residual; block-wide zero fast path. WARM=12.
// B=64, T=1000, F=140, D=256, K=7, tau=2, v_th=1, hard reset.
// ---------------------------------------------------------------------------

#define B_    64
#define T_    1000
#define F_    140
#define D_    256
#define K_    7
#define NCH   10
#define CLEN  100
#define WARM1 12
#define WARM2 12
#define SMT   (CLEN + WARM2)
#define ASTR  12

__device__ __nv_bfloat16 g_ybf[(size_t)B_ * T_ * D_];  // GEMM out (B,T,D) bf16
__device__ float         g_linT[D_ * D_];              // lin_w^T [d][e]

__device__ __forceinline__ unsigned pack_bf16(float lo, float hi) {
    __nv_bfloat162 h = __floats2bfloat162_rn(lo, hi);
    return *reinterpret_cast<unsigned*>(&h);
}

__device__ __forceinline__ uint32_t smem_u32(const void* p) {
    uint32_t a;
    asm("{ .reg .u64 t; cvta.to.shared.u64 t, %1; cvt.u32.u64 %0, t; }"
        : "=r"(a) : "l"(p));
    return a;
}

#define LDSM_X4(r0, r1, r2, r3, addr)                                         \
    asm volatile("ldmatrix.sync.aligned.m8n8.x4.shared.b16 {%0,%1,%2,%3}, [%4];" \
        : "=r"(r0), "=r"(r1), "=r"(r2), "=r"(r3) : "r"(addr))

// ---------------------------------------------------------------------------
// GEMM1: y[m,n] = x[m,:].pw_w[n,:], M=64000 N=256 K=140, BM=128 BN=128.
// 8 warps (wm{0,1} x wn{0..3}), 9 k-steps, 1 sync/step, double buffer.
// ---------------------------------------------------------------------------
__global__ __launch_bounds__(256) void k_gemm1(const float* __restrict__ x,
                                               const float* __restrict__ w,
                                               const float* __restrict__ linw) {
    __shared__ __align__(16) unsigned As[2][128 * ASTR];
    __shared__ __align__(16) unsigned Bs[2][128 * ASTR];

    const int tid = threadIdx.x;
    const int m0  = blockIdx.x * 128;
    const int n0  = blockIdx.y * 128;

    // folded TILED transpose of lin_w (first 64 blocks of y==0 slice)
    if (blockIdx.y == 0 && blockIdx.x < 64) {
        float* ts = reinterpret_cast<float*>(&As[0][0]);
        const int bi = blockIdx.x & 7, bj = blockIdx.x >> 3;
        const int tx = tid & 31, ty0 = tid >> 5;
        #pragma unroll
        for (int r = 0; r < 4; r++) {
            int ty = ty0 + 8 * r;
            ts[ty * 33 + tx] = linw[(size_t)(bj * 32 + ty) * D_ + bi * 32 + tx];
        }
        __syncthreads();
        #pragma unroll
        for (int r = 0; r < 4; r++) {
            int ty = ty0 + 8 * r;
            g_linT[(size_t)(bi * 32 + ty) * D_ + bj * 32 + tx] = ts[tx * 33 + ty];
        }
        __syncthreads();
    }

    const int warp = tid >> 5, lane = tid & 31;
    const int wm   = warp >> 2;
    const int wn   = warp & 3;
    const int g    = lane >> 2, tig = lane & 3;

    const int r0i = tid >> 2, r1i = (tid + 256) >> 2, aq = tid & 3;

    // staging regs: A has two sets (2-step), B one set (1-step)
    float4 pa0[2], pa1[2];
    float4 pb0, pb1;

    auto ldgA = [&](int s, int r) {
        const int k = s * 16 + aq * 4;
        pa0[r] = (k < F_) ? *(const float4*)&x[(size_t)(m0 + r0i) * F_ + k]
                          : make_float4(0.f, 0.f, 0.f, 0.f);
        pa1[r] = (k < F_) ? *(const float4*)&x[(size_t)(m0 + r1i) * F_ + k]
                          : make_float4(0.f, 0.f, 0.f, 0.f);
    };
    auto ldgB = [&](int s) {
        const int k = s * 16 + aq * 4;
        pb0 = (k < F_) ? *(const float4*)&w[(size_t)(n0 + r0i) * F_ + k]
                       : make_float4(0.f, 0.f, 0.f, 0.f);
        pb1 = (k < F_) ? *(const float4*)&w[(size_t)(n0 + r1i) * F_ + k]
                       : make_float4(0.f, 0.f, 0.f, 0.f);
    };
    auto stsA = [&](int buf, int r) {
        As[buf][r0i * ASTR + aq * 2]     = pack_bf16(pa0[r].x, pa0[r].y);
        As[buf][r0i * ASTR + aq * 2 + 1] = pack_bf16(pa0[r].z, pa0[r].w);
        As[buf][r1i * ASTR + aq * 2]     = pack_bf16(pa1[r].x, pa1[r].y);
        As[buf][r1i * ASTR + aq * 2 + 1] = pack_bf16(pa1[r].z, pa1[r].w);
    };
    auto stsB = [&](int buf) {
        Bs[buf][r0i * ASTR + aq * 2]     = pack_bf16(pb0.x, pb0.y);
        Bs[buf][r0i * ASTR + aq * 2 + 1] = pack_bf16(pb0.z, pb0.w);
        Bs[buf][r1i * ASTR + aq * 2]     = pack_bf16(pb1.x, pb1.y);
        Bs[buf][r1i * ASTR + aq * 2 + 1] = pack_bf16(pb1.z, pb1.w);
    };

    // ldmatrix per-lane byte offsets (constant across steps; parity = buffer)
    const unsigned asu[2] = { smem_u32(&As[0][0]), smem_u32(&As[1][0]) };
    const unsigned bsu[2] = { smem_u32(&Bs[0][0]), smem_u32(&Bs[1][0]) };
    unsigned aOff[4], bOff[2];
    #pragma unroll
    for (int mi = 0; mi < 4; mi++)
        aOff[mi] = (unsigned)((wm * 64 + mi * 16 + (lane & 15)) * (ASTR * 4) +
                              ((lane & 16) ? 16 : 0));
    #pragma unroll
    for (int nj = 0; nj < 2; nj++)
        bOff[nj] = (unsigned)((wn * 32 + nj * 16 + ((lane >> 4) & 1) * 8 +
                               (lane & 7)) * (ASTR * 4) +
                              ((lane & 8) ? 16 : 0));

    float c[4][4][4];
    #pragma unroll
    for (int i = 0; i < 4; i++)
        #pragma unroll
        for (int j = 0; j < 4; j++)
            #pragma unroll
            for (int r = 0; r < 4; r++) c[i][j][r] = 0.f;

    // preamble: step0 staged into buf0; A step1 into reg set 0
    ldgA(0, 0);
    ldgB(0);
    stsA(0, 0);
    stsB(0);
    ldgA(1, 0);
    __syncthreads();

    int p = 0;
    for (int s = 0; s < 9; ++s) {
        if (s < 7) ldgA(s + 2, (s + 1) & 1);   // A: 2 steps ahead
        if (s < 8) ldgB(s + 1);                // B: 1 step ahead (L2-hot)

        unsigned a[4][4], bf[4][2];
        #pragma unroll
        for (int mi = 0; mi < 4; mi++)
            LDSM_X4(a[mi][0], a[mi][1], a[mi][2], a[mi][3], asu[p] + aOff[mi]);
        #pragma unroll
        for (int nj = 0; nj < 2; nj++)
            LDSM_X4(bf[2 * nj][0], bf[2 * nj][1], bf[2 * nj + 1][0],
                    bf[2 * nj + 1][1], bsu[p] + bOff[nj]);

        #pragma unroll
        for (int mi = 0; mi < 4; mi++)
            #pragma unroll
            for (int ni = 0; ni < 4; ni++) {
                asm volatile(
                    "mma.sync.aligned.m16n8k16.row.col.f32.bf16.bf16.f32 "
                    "{%0,%1,%2,%3}, {%4,%5,%6,%7}, {%8,%9}, {%0,%1,%2,%3};\n"
                    : "+f"(c[mi][ni][0]), "+f"(c[mi][ni][1]),
                      "+f"(c[mi][ni][2]), "+f"(c[mi][ni][3])
                    : "r"(a[mi][0]), "r"(a[mi][1]), "r"(a[mi][2]), "r"(a[mi][3]),
                      "r"(bf[ni][0]), "r"(bf[ni][1]));
            }

        if (s < 8) {
            stsA(1 - p, s & 1);
            stsB(1 - p);
        }
        __syncthreads();
        p ^= 1;
    }

    // epilogue: pack bf16 pairs, store as u32
    unsigned* yw = reinterpret_cast<unsigned*>(g_ybf);
    #pragma unroll
    for (int mi = 0; mi < 4; mi++) {
        int r0 = m0 + wm * 64 + mi * 16 + g;
        #pragma unroll
        for (int ni = 0; ni < 4; ni++) {
            int col = n0 + wn * 32 + ni * 8 + 2 * tig;
            yw[((size_t)r0 * D_ + col) >> 1] =
                pack_bf16(c[mi][ni][0], c[mi][ni][1]);
            yw[((size_t)(r0 + 8) * D_ + col) >> 1] =
                pack_bf16(c[mi][ni][2], c[mi][ni][3]);
        }
    }
}

// ---------------------------------------------------------------------------
// fused LIF kernel: grid (B, NCH) x 256 threads
// ---------------------------------------------------------------------------
template <bool GUARD>
__device__ __forceinline__ void lif1_main(const __nv_bfloat16* __restrict__ yp,
                                          const float* ac, float base,
                                          float& v, float& w0, float& w1,
                                          float& w2, float& w3, float& w4,
                                          float& w5, float& w6,
                                          int ts2, int tend, unsigned* smk,
                                          unsigned& locOr, int warp, int lane) {
    for (int t0 = ts2; t0 < tend; t0 += 4) {
        float nf[4];
        #pragma unroll
        for (int j = 0; j < 4; j++) {
            int t = t0 + 4 + j;
            if (GUARD)
                nf[j] = (t < T_) ? __bfloat162float(yp[(size_t)t * D_]) : 0.f;
            else
                nf[j] = __bfloat162float(yp[(size_t)t * D_]);
        }
        #pragma unroll
        for (int j = 0; j < 4; j++) {
            float acc = base;
            acc = fmaf(w0, ac[0], acc); acc = fmaf(w1, ac[1], acc);
            acc = fmaf(w2, ac[2], acc); acc = fmaf(w3, ac[3], acc);
            acc = fmaf(w4, ac[4], acc); acc = fmaf(w5, ac[5], acc);
            acc = fmaf(w6, ac[6], acc);
            v = fmaf(v, 0.5f, acc);
            bool s = (v >= 1.0f);
            unsigned bal = __ballot_sync(0xffffffffu, s);
            if (s) v = 0.f;
            if (lane == 0) { smk[(t0 + j - ts2) * 8 + warp] = bal; locOr |= bal; }
            w0 = w1; w1 = w2; w2 = w3; w3 = w4; w4 = w5; w5 = w6; w6 = nf[j];
        }
    }
}

__global__ __launch_bounds__(256) void k_lif(const float* __restrict__ pw_b,
                                             const float* __restrict__ dw,
                                             const float* __restrict__ g1,
                                             const float* __restrict__ b1,
                                             const float* __restrict__ m1,
                                             const float* __restrict__ v1,
                                             const float* __restrict__ g2,
                                             const float* __restrict__ b2,
                                             const float* __restrict__ m2,
                                             const float* __restrict__ v2p,
                                             float* __restrict__ out) {
    __shared__ unsigned smk[SMT * 8];
    __shared__ unsigned s_any;
    __shared__ unsigned s_hot;

    const int b    = blockIdx.x;
    const int ch   = blockIdx.y;
    const int d    = threadIdx.x;
    const int lane = d & 31;
    const int warp = d >> 5;

    const int tstart = ch * CLEN;
    const int tend   = tstart + CLEN;
    const int ts2    = (ch == 0) ? 0 : tstart - WARM2;
    const int ts1    = (ch == 0) ? 0 : ts2 - WARM1;

    if (d == 0) { s_any = 0u; s_hot = 0u; }

    const float scale2 = g2[d] * rsqrtf(v2p[d] + 1e-5f);
    const float shift2 = b2[d] - m2[d] * scale2;
    {
        unsigned hot = __ballot_sync(0xffffffffu, shift2 >= 1.0f);
        if (lane == 0 && hot) atomicOr(&s_hot, hot);
    }

    // ---- phase 1: depthwise conv + BN1 + LIF1 ----
    {
        const float bias  = pw_b[d];
        const float scale = g1[d] * rsqrtf(v1[d] + 1e-5f);
        const float shift = b1[d] - m1[d] * scale;

        float ac[K_];
        float suma = 0.f;
        #pragma unroll
        for (int k = 0; k < K_; k++) {
            float a = dw[d * K_ + k];
            suma += a;
            ac[k] = 0.5f * scale * a;
        }
        const float base = 0.5f * (scale * bias * suma + shift);

        const __nv_bfloat16* yp = g_ybf + (size_t)b * T_ * D_ + d;

        float w0, w1, w2, w3, w4, w5, w6;
        {
            float wv[7];
            #pragma unroll
            for (int j = 0; j < 7; j++) {
                int t = ts1 - 3 + j;
                wv[j] = (t >= 0) ? __bfloat162float(yp[(size_t)t * D_]) : 0.f;
            }
            w0 = wv[0]; w1 = wv[1]; w2 = wv[2]; w3 = wv[3];
            w4 = wv[4]; w5 = wv[5]; w6 = wv[6];
        }

        float v = 0.f;
        for (int t0 = ts1; t0 < ts2; t0 += 4) {
            float nf[4];
            #pragma unroll
            for (int j = 0; j < 4; j++)
                nf[j] = __bfloat162float(yp[(size_t)(t0 + 4 + j) * D_]);
            #pragma unroll
            for (int j = 0; j < 4; j++) {
                float acc = base;
                acc = fmaf(w0, ac[0], acc); acc = fmaf(w1, ac[1], acc);
                acc = fmaf(w2, ac[2], acc); acc = fmaf(w3, ac[3], acc);
                acc = fmaf(w4, ac[4], acc); acc = fmaf(w5, ac[5], acc);
                acc = fmaf(w6, ac[6], acc);
                v = fmaf(v, 0.5f, acc);
                if (v >= 1.0f) v = 0.f;
                w0 = w1; w1 = w2; w2 = w3; w3 = w4; w4 = w5; w5 = w6; w6 = nf[j];
            }
        }

        unsigned locOr = 0u;
        if (ch == NCH - 1)
            lif1_main<true >(yp, ac, base, v, w0, w1, w2, w3, w4, w5, w6,
                             ts2, tend, smk, locOr, warp, lane);
        else
            lif1_main<false>(yp, ac, base, v, w0, w1, w2, w3, w4, w5, w6,
                             ts2, tend, smk, locOr, warp, lane);

        if (lane == 0 && locOr) atomicOr(&s_any, locOr);
    }
    __syncthreads();

    // ---- phase 2: sparse linear + BN2 + LIF2 + residual ----
    if (s_any == 0u) {
        if (s_hot == 0u) {
            float4* ob = (float4*)(out + (size_t)tstart * (B_ * D_) +
                                   (size_t)b * D_) + (d & 63);
            const int tof = d >> 6;
            const float4 z = make_float4(0.f, 0.f, 0.f, 0.f);
            #pragma unroll
            for (int jj = 0; jj < CLEN / 4; ++jj)
                ob[(size_t)(jj * 4 + tof) * (B_ * D_ / 4)] = z;
        } else {
            float* op = out + (size_t)tstart * (B_ * D_) + (size_t)b * D_ + d;
            if (shift2 < 1.0f) {
                #pragma unroll 10
                for (int j = 0; j < CLEN; ++j)
                    op[(size_t)j * (B_ * D_)] = 0.f;
            } else {
                float v = 0.f;
                const float hs = 0.5f * shift2;
                for (int j = 0; j < tstart - ts2; ++j) {
                    v = fmaf(v, 0.5f, hs);
                    if (v >= 1.0f) v = 0.f;
                }
                #pragma unroll 10
                for (int j = 0; j < CLEN; ++j) {
                    v = fmaf(v, 0.5f, hs);
                    float sp = 0.f;
                    if (v >= 1.0f) { sp = 1.f; v = 0.f; }
                    op[(size_t)j * (B_ * D_)] = sp;
                }
            }
        }
        return;
    }

    // slow path: spikes present in window
    const int e = d;
    const int      myw   = e >> 5;
    const unsigned mybit = 1u << (e & 31);
    float v = 0.f;

    for (int t = ts2; t < tend; ++t) {
        const int o = (t - ts2) * 8;
        uint4 p0 = *(const uint4*)&smk[o];
        uint4 p1 = *(const uint4*)&smk[o + 4];
        unsigned any = p0.x | p0.y | p0.z | p0.w | p1.x | p1.y | p1.z | p1.w;

        float acc = 0.f, res = 0.f;
        if (any) {
            unsigned wds[8] = {p0.x, p0.y, p0.z, p0.w, p1.x, p1.y, p1.z, p1.w};
            #pragma unroll
            for (int i = 0; i < 8; i++) {
                unsigned wd = wds[i];
                if (i == myw && (wd & mybit)) res = 1.f;
                while (wd) {
                    int bit = __ffs(wd) - 1;
                    wd &= wd - 1;
                    acc += g_linT[(size_t)(i * 32 + bit) * D_ + e];
                }
            }
        }

        float u = fmaf(acc, scale2, shift2);
        v = 0.5f * (v + u);
        float sp = 0.f;
        if (v >= 1.0f) { sp = 1.f; v = 0.f; }

        if (t >= tstart)
            out[((size_t)t * B_ + b) * D_ + e] = sp + res;
    }
}

// ---------------------------------------------------------------------------
// inputs: 0:x 1:pw_w 2:pw_b 3:dw_w 4:bn1_g 5:bn1_b 6:bn1_m 7:bn1_v
//         8:lin_w 9:bn2_g 10:bn2_b 11:bn2_m 12:bn2_v
// ---------------------------------------------------------------------------
extern "C" void kernel_launch(void* const* d_in, const int* in_sizes, int n_in,
                              void* d_out, int out_size) {
    const float* x    = (const float*)d_in[0];
    const float* pw_w = (const float*)d_in[1];
    const float* pw_b = (const float*)d_in[2];
    const float* dw_w = (const float*)d_in[3];
    const float* g1   = (const float*)d_in[4];
    const float* b1   = (const float*)d_in[5];
    const float* m1   = (const float*)d_in[6];
    const float* v1   = (const float*)d_in[7];
    const float* linw = (const float*)d_in[8];
    const float* g2   = (const float*)d_in[9];
    const float* b2   = (const float*)d_in[10];
    const float* m2   = (const float*)d_in[11];
    const float* v2   = (const float*)d_in[12];
    float* out = (float*)d_out;

    dim3 gg((B_ * T_) / 128, D_ / 128);   // (500, 2)
    k_gemm1<<<gg, 256>>>(x, pw_w, linw);

    dim3 gl(B_, NCH);
    k_lif<<<gl, 256>>>(pw_b, dw_w, g1, b1, m1, v1, g2, b2, m2, v2, out);
}

// round 16
// speedup vs baseline: 1.0846x; 1.0846x over previous
#include <cuda_runtime.h>
#include <cuda_bf16.h>
#include <cstdint>

// ---------------------------------------------------------------------------
// SEE block on GB300 — split architecture, 2 launches.
// k_gemm1: bf16 mma.sync, BM=128 BN=128. Full-K B tile staged ONCE per block
//          into dynamic smem (54 KB, ldmatrix layout); A double-buffered with
//          2-step LDG prefetch. Steady loop: A-stage + ldmatrix + mma only.
//          First 64 blocks fold a tiled transpose of lin_w. y stored bf16.
// k_lif  : depthwise conv+BN+LIF1 -> masks in smem -> sparse linear+BN+LIF2
//          +residual; block-wide zero fast path. WARM=12.
// B=64, T=1000, F=140, D=256, K=7, tau=2, v_th=1, hard reset.
// ---------------------------------------------------------------------------

#define B_    64
#define T_    1000
#define F_    140
#define D_    256
#define K_    7
#define NCH   10
#define CLEN  100
#define WARM1 12
#define WARM2 12
#define SMT   (CLEN + WARM2)
#define ASTR  12

// dynamic smem layout (u32 units)
#define OFF_B   0                    // 9 * 128 * ASTR = 13824 u32 (55296 B)
#define OFF_A   (9 * 128 * ASTR)     // 2 * 128 * ASTR =  3072 u32 (12288 B)
#define GSM_U32 (OFF_A + 2 * 128 * ASTR)
#define GSM_BYTES (GSM_U32 * 4)

__device__ __nv_bfloat16 g_ybf[(size_t)B_ * T_ * D_];  // GEMM out (B,T,D) bf16
__device__ float         g_linT[D_ * D_];              // lin_w^T [d][e]

__device__ __forceinline__ unsigned pack_bf16(float lo, float hi) {
    __nv_bfloat162 h = __floats2bfloat162_rn(lo, hi);
    return *reinterpret_cast<unsigned*>(&h);
}

__device__ __forceinline__ uint32_t smem_u32(const void* p) {
    uint32_t a;
    asm("{ .reg .u64 t; cvta.to.shared.u64 t, %1; cvt.u32.u64 %0, t; }"
        : "=r"(a) : "l"(p));
    return a;
}

#define LDSM_X4(r0, r1, r2, r3, addr)                                         \
    asm volatile("ldmatrix.sync.aligned.m8n8.x4.shared.b16 {%0,%1,%2,%3}, [%4];" \
        : "=r"(r0), "=r"(r1), "=r"(r2), "=r"(r3) : "r"(addr))

// ---------------------------------------------------------------------------
// GEMM1: y[m,n] = x[m,:].pw_w[n,:], M=64000 N=256 K=140, BM=128 BN=128.
// 8 warps (wm{0,1} x wn{0..3}), 9 k-steps, 1 sync/step (A double buffer).
// ---------------------------------------------------------------------------
__global__ __launch_bounds__(256) void k_gemm1(const float* __restrict__ x,
                                               const float* __restrict__ w,
                                               const float* __restrict__ linw) {
    extern __shared__ __align__(16) unsigned sh[];

    const int tid = threadIdx.x;
    const int m0  = blockIdx.x * 128;
    const int n0  = blockIdx.y * 128;

    // folded TILED transpose of lin_w (first 64 blocks of y==0 slice),
    // scratch = A region (12 KB > 4.2 KB needed)
    if (blockIdx.y == 0 && blockIdx.x < 64) {
        float* ts = reinterpret_cast<float*>(sh + OFF_A);
        const int bi = blockIdx.x & 7, bj = blockIdx.x >> 3;
        const int tx = tid & 31, ty0 = tid >> 5;
        #pragma unroll
        for (int r = 0; r < 4; r++) {
            int ty = ty0 + 8 * r;
            ts[ty * 33 + tx] = linw[(size_t)(bj * 32 + ty) * D_ + bi * 32 + tx];
        }
        __syncthreads();
        #pragma unroll
        for (int r = 0; r < 4; r++) {
            int ty = ty0 + 8 * r;
            g_linT[(size_t)(bi * 32 + ty) * D_ + bj * 32 + tx] = ts[tx * 33 + ty];
        }
        __syncthreads();
    }

    const int warp = tid >> 5, lane = tid & 31;
    const int wm   = warp >> 2;
    const int wn   = warp & 3;
    const int g    = lane >> 2, tig = lane & 3;

    const int r0i = tid >> 2, r1i = (tid + 256) >> 2, aq = tid & 3;

    // ---- one-time: stage FULL-K B tile (fp32 -> bf16, ldmatrix layout) ----
    {
        float4 wb0[9], wb1[9];
        #pragma unroll
        for (int s = 0; s < 9; s++) {
            int k = s * 16 + aq * 4;
            wb0[s] = (k < F_) ? *(const float4*)&w[(size_t)(n0 + r0i) * F_ + k]
                              : make_float4(0.f, 0.f, 0.f, 0.f);
            wb1[s] = (k < F_) ? *(const float4*)&w[(size_t)(n0 + r1i) * F_ + k]
                              : make_float4(0.f, 0.f, 0.f, 0.f);
        }
        #pragma unroll
        for (int s = 0; s < 9; s++) {
            unsigned* Bp = sh + OFF_B + s * (128 * ASTR);
            Bp[r0i * ASTR + aq * 2]     = pack_bf16(wb0[s].x, wb0[s].y);
            Bp[r0i * ASTR + aq * 2 + 1] = pack_bf16(wb0[s].z, wb0[s].w);
            Bp[r1i * ASTR + aq * 2]     = pack_bf16(wb1[s].x, wb1[s].y);
            Bp[r1i * ASTR + aq * 2 + 1] = pack_bf16(wb1[s].z, wb1[s].w);
        }
    }

    // ---- A staging: two register sets, 2-step prefetch ----
    float4 pa0[2], pa1[2];
    auto ldgA = [&](int s, int r) {
        const int k = s * 16 + aq * 4;
        pa0[r] = (k < F_) ? *(const float4*)&x[(size_t)(m0 + r0i) * F_ + k]
                          : make_float4(0.f, 0.f, 0.f, 0.f);
        pa1[r] = (k < F_) ? *(const float4*)&x[(size_t)(m0 + r1i) * F_ + k]
                          : make_float4(0.f, 0.f, 0.f, 0.f);
    };
    auto stsA = [&](int buf, int r) {
        unsigned* Ap = sh + OFF_A + buf * (128 * ASTR);
        Ap[r0i * ASTR + aq * 2]     = pack_bf16(pa0[r].x, pa0[r].y);
        Ap[r0i * ASTR + aq * 2 + 1] = pack_bf16(pa0[r].z, pa0[r].w);
        Ap[r1i * ASTR + aq * 2]     = pack_bf16(pa1[r].x, pa1[r].y);
        Ap[r1i * ASTR + aq * 2 + 1] = pack_bf16(pa1[r].z, pa1[r].w);
    };

    // ldmatrix base addresses + per-lane offsets
    const unsigned asu[2] = { smem_u32(sh + OFF_A),
                              smem_u32(sh + OFF_A + 128 * ASTR) };
    const unsigned bsu = smem_u32(sh + OFF_B);
    unsigned aOff[4], bOff[2];
    #pragma unroll
    for (int mi = 0; mi < 4; mi++)
        aOff[mi] = (unsigned)((wm * 64 + mi * 16 + (lane & 15)) * (ASTR * 4) +
                              ((lane & 16) ? 16 : 0));
    #pragma unroll
    for (int nj = 0; nj < 2; nj++)
        bOff[nj] = (unsigned)((wn * 32 + nj * 16 + ((lane >> 4) & 1) * 8 +
                               (lane & 7)) * (ASTR * 4) +
                              ((lane & 8) ? 16 : 0));

    float c[4][4][4];
    #pragma unroll
    for (int i = 0; i < 4; i++)
        #pragma unroll
        for (int j = 0; j < 4; j++)
            #pragma unroll
            for (int r = 0; r < 4; r++) c[i][j][r] = 0.f;

    // preamble: A step0 -> buf0; A step1 -> reg set 0
    ldgA(0, 0);
    stsA(0, 0);
    ldgA(1, 0);
    __syncthreads();      // covers B tile + A buf0

    int p = 0;
    #pragma unroll
    for (int s = 0; s < 9; ++s) {
        if (s < 7) ldgA(s + 2, (s + 1) & 1);   // A: 2 steps ahead

        unsigned a[4][4], bf[4][2];
        #pragma unroll
        for (int mi = 0; mi < 4; mi++)
            LDSM_X4(a[mi][0], a[mi][1], a[mi][2], a[mi][3], asu[p] + aOff[mi]);
        const unsigned bstep = bsu + (unsigned)(s * 128 * ASTR * 4);
        #pragma unroll
        for (int nj = 0; nj < 2; nj++)
            LDSM_X4(bf[2 * nj][0], bf[2 * nj][1], bf[2 * nj + 1][0],
                    bf[2 * nj + 1][1], bstep + bOff[nj]);

        #pragma unroll
        for (int mi = 0; mi < 4; mi++)
            #pragma unroll
            for (int ni = 0; ni < 4; ni++) {
                asm volatile(
                    "mma.sync.aligned.m16n8k16.row.col.f32.bf16.bf16.f32 "
                    "{%0,%1,%2,%3}, {%4,%5,%6,%7}, {%8,%9}, {%0,%1,%2,%3};\n"
                    : "+f"(c[mi][ni][0]), "+f"(c[mi][ni][1]),
                      "+f"(c[mi][ni][2]), "+f"(c[mi][ni][3])
                    : "r"(a[mi][0]), "r"(a[mi][1]), "r"(a[mi][2]), "r"(a[mi][3]),
                      "r"(bf[ni][0]), "r"(bf[ni][1]));
            }

        if (s < 8) stsA(1 - p, s & 1);         // stash A step s+1
        __syncthreads();
        p ^= 1;
    }

    // epilogue: pack bf16 pairs, store as u32
    unsigned* yw = reinterpret_cast<unsigned*>(g_ybf);
    #pragma unroll
    for (int mi = 0; mi < 4; mi++) {
        int r0 = m0 + wm * 64 + mi * 16 + g;
        #pragma unroll
        for (int ni = 0; ni < 4; ni++) {
            int col = n0 + wn * 32 + ni * 8 + 2 * tig;
            yw[((size_t)r0 * D_ + col) >> 1] =
                pack_bf16(c[mi][ni][0], c[mi][ni][1]);
            yw[((size_t)(r0 + 8) * D_ + col) >> 1] =
                pack_bf16(c[mi][ni][2], c[mi][ni][3]);
        }
    }
}

// ---------------------------------------------------------------------------
// fused LIF kernel: grid (B, NCH) x 256 threads
// ---------------------------------------------------------------------------
template <bool GUARD>
__device__ __forceinline__ void lif1_main(const __nv_bfloat16* __restrict__ yp,
                                          const float* ac, float base,
                                          float& v, float& w0, float& w1,
                                          float& w2, float& w3, float& w4,
                                          float& w5, float& w6,
                                          int ts2, int tend, unsigned* smk,
                                          unsigned& locOr, int warp, int lane) {
    for (int t0 = ts2; t0 < tend; t0 += 4) {
        float nf[4];
        #pragma unroll
        for (int j = 0; j < 4; j++) {
            int t = t0 + 4 + j;
            if (GUARD)
                nf[j] = (t < T_) ? __bfloat162float(yp[(size_t)t * D_]) : 0.f;
            else
                nf[j] = __bfloat162float(yp[(size_t)t * D_]);
        }
        #pragma unroll
        for (int j = 0; j < 4; j++) {
            float acc = base;
            acc = fmaf(w0, ac[0], acc); acc = fmaf(w1, ac[1], acc);
            acc = fmaf(w2, ac[2], acc); acc = fmaf(w3, ac[3], acc);
            acc = fmaf(w4, ac[4], acc); acc = fmaf(w5, ac[5], acc);
            acc = fmaf(w6, ac[6], acc);
            v = fmaf(v, 0.5f, acc);
            bool s = (v >= 1.0f);
            unsigned bal = __ballot_sync(0xffffffffu, s);
            if (s) v = 0.f;
            if (lane == 0) { smk[(t0 + j - ts2) * 8 + warp] = bal; locOr |= bal; }
            w0 = w1; w1 = w2; w2 = w3; w3 = w4; w4 = w5; w5 = w6; w6 = nf[j];
        }
    }
}

__global__ __launch_bounds__(256) void k_lif(const float* __restrict__ pw_b,
                                             const float* __restrict__ dw,
                                             const float* __restrict__ g1,
                                             const float* __restrict__ b1,
                                             const float* __restrict__ m1,
                                             const float* __restrict__ v1,
                                             const float* __restrict__ g2,
                                             const float* __restrict__ b2,
                                             const float* __restrict__ m2,
                                             const float* __restrict__ v2p,
                                             float* __restrict__ out) {
    __shared__ unsigned smk[SMT * 8];
    __shared__ unsigned s_any;
    __shared__ unsigned s_hot;

    const int b    = blockIdx.x;
    const int ch   = blockIdx.y;
    const int d    = threadIdx.x;
    const int lane = d & 31;
    const int warp = d >> 5;

    const int tstart = ch * CLEN;
    const int tend   = tstart + CLEN;
    const int ts2    = (ch == 0) ? 0 : tstart - WARM2;
    const int ts1    = (ch == 0) ? 0 : ts2 - WARM1;

    if (d == 0) { s_any = 0u; s_hot = 0u; }

    const float scale2 = g2[d] * rsqrtf(v2p[d] + 1e-5f);
    const float shift2 = b2[d] - m2[d] * scale2;
    {
        unsigned hot = __ballot_sync(0xffffffffu, shift2 >= 1.0f);
        if (lane == 0 && hot) atomicOr(&s_hot, hot);
    }

    // ---- phase 1: depthwise conv + BN1 + LIF1 ----
    {
        const float bias  = pw_b[d];
        const float scale = g1[d] * rsqrtf(v1[d] + 1e-5f);
        const float shift = b1[d] - m1[d] * scale;

        float ac[K_];
        float suma = 0.f;
        #pragma unroll
        for (int k = 0; k < K_; k++) {
            float a = dw[d * K_ + k];
            suma += a;
            ac[k] = 0.5f * scale * a;
        }
        const float base = 0.5f * (scale * bias * suma + shift);

        const __nv_bfloat16* yp = g_ybf + (size_t)b * T_ * D_ + d;

        float w0, w1, w2, w3, w4, w5, w6;
        {
            float wv[7];
            #pragma unroll
            for (int j = 0; j < 7; j++) {
                int t = ts1 - 3 + j;
                wv[j] = (t >= 0) ? __bfloat162float(yp[(size_t)t * D_]) : 0.f;
            }
            w0 = wv[0]; w1 = wv[1]; w2 = wv[2]; w3 = wv[3];
            w4 = wv[4]; w5 = wv[5]; w6 = wv[6];
        }

        float v = 0.f;
        for (int t0 = ts1; t0 < ts2; t0 += 4) {
            float nf[4];
            #pragma unroll
            for (int j = 0; j < 4; j++)
                nf[j] = __bfloat162float(yp[(size_t)(t0 + 4 + j) * D_]);
            #pragma unroll
            for (int j = 0; j < 4; j++) {
                float acc = base;
                acc = fmaf(w0, ac[0], acc); acc = fmaf(w1, ac[1], acc);
                acc = fmaf(w2, ac[2], acc); acc = fmaf(w3, ac[3], acc);
                acc = fmaf(w4, ac[4], acc); acc = fmaf(w5, ac[5], acc);
                acc = fmaf(w6, ac[6], acc);
                v = fmaf(v, 0.5f, acc);
                if (v >= 1.0f) v = 0.f;
                w0 = w1; w1 = w2; w2 = w3; w3 = w4; w4 = w5; w5 = w6; w6 = nf[j];
            }
        }

        unsigned locOr = 0u;
        if (ch == NCH - 1)
            lif1_main<true >(yp, ac, base, v, w0, w1, w2, w3, w4, w5, w6,
                             ts2, tend, smk, locOr, warp, lane);
        else
            lif1_main<false>(yp, ac, base, v, w0, w1, w2, w3, w4, w5, w6,
                             ts2, tend, smk, locOr, warp, lane);

        if (lane == 0 && locOr) atomicOr(&s_any, locOr);
    }
    __syncthreads();

    // ---- phase 2: sparse linear + BN2 + LIF2 + residual ----
    if (s_any == 0u) {
        if (s_hot == 0u) {
            float4* ob = (float4*)(out + (size_t)tstart * (B_ * D_) +
                                   (size_t)b * D_) + (d & 63);
            const int tof = d >> 6;
            const float4 z = make_float4(0.f, 0.f, 0.f, 0.f);
            #pragma unroll
            for (int jj = 0; jj < CLEN / 4; ++jj)
                ob[(size_t)(jj * 4 + tof) * (B_ * D_ / 4)] = z;
        } else {
            float* op = out + (size_t)tstart * (B_ * D_) + (size_t)b * D_ + d;
            if (shift2 < 1.0f) {
                #pragma unroll 10
                for (int j = 0; j < CLEN; ++j)
                    op[(size_t)j * (B_ * D_)] = 0.f;
            } else {
                float v = 0.f;
                const float hs = 0.5f * shift2;
                for (int j = 0; j < tstart - ts2; ++j) {
                    v = fmaf(v, 0.5f, hs);
                    if (v >= 1.0f) v = 0.f;
                }
                #pragma unroll 10
                for (int j = 0; j < CLEN; ++j) {
                    v = fmaf(v, 0.5f, hs);
                    float sp = 0.f;
                    if (v >= 1.0f) { sp = 1.f; v = 0.f; }
                    op[(size_t)j * (B_ * D_)] = sp;
                }
            }
        }
        return;
    }

    // slow path: spikes present in window
    const int e = d;
    const int      myw   = e >> 5;
    const unsigned mybit = 1u << (e & 31);
    float v = 0.f;

    for (int t = ts2; t < tend; ++t) {
        const int o = (t - ts2) * 8;
        uint4 p0 = *(const uint4*)&smk[o];
        uint4 p1 = *(const uint4*)&smk[o + 4];
        unsigned any = p0.x | p0.y | p0.z | p0.w | p1.x | p1.y | p1.z | p1.w;

        float acc = 0.f, res = 0.f;
        if (any) {
            unsigned wds[8] = {p0.x, p0.y, p0.z, p0.w, p1.x, p1.y, p1.z, p1.w};
            #pragma unroll
            for (int i = 0; i < 8; i++) {
                unsigned wd = wds[i];
                if (i == myw && (wd & mybit)) res = 1.f;
                while (wd) {
                    int bit = __ffs(wd) - 1;
                    wd &= wd - 1;
                    acc += g_linT[(size_t)(i * 32 + bit) * D_ + e];
                }
            }
        }

        float u = fmaf(acc, scale2, shift2);
        v = 0.5f * (v + u);
        float sp = 0.f;
        if (v >= 1.0f) { sp = 1.f; v = 0.f; }

        if (t >= tstart)
            out[((size_t)t * B_ + b) * D_ + e] = sp + res;
    }
}

// ---------------------------------------------------------------------------
// inputs: 0:x 1:pw_w 2:pw_b 3:dw_w 4:bn1_g 5:bn1_b 6:bn1_m 7:bn1_v
//         8:lin_w 9:bn2_g 10:bn2_b 11:bn2_m 12:bn2_v
// ---------------------------------------------------------------------------
extern "C" void kernel_launch(void* const* d_in, const int* in_sizes, int n_in,
                              void* d_out, int out_size) {
    const float* x    = (const float*)d_in[0];
    const float* pw_w = (const float*)d_in[1];
    const float* pw_b = (const float*)d_in[2];
    const float* dw_w = (const float*)d_in[3];
    const float* g1   = (const float*)d_in[4];
    const float* b1   = (const float*)d_in[5];
    const float* m1   = (const float*)d_in[6];
    const float* v1   = (const float*)d_in[7];
    const float* linw = (const float*)d_in[8];
    const float* g2   = (const float*)d_in[9];
    const float* b2   = (const float*)d_in[10];
    const float* m2   = (const float*)d_in[11];
    const float* v2   = (const float*)d_in[12];
    float* out = (float*)d_out;

    cudaFuncSetAttribute(k_gemm1, cudaFuncAttributeMaxDynamicSharedMemorySize,
                         GSM_BYTES);

    dim3 gg((B_ * T_) / 128, D_ / 128);   // (500, 2)
    k_gemm1<<<gg, 256, GSM_BYTES>>>(x, pw_w, linw);

    dim3 gl(B_, NCH);
    k_lif<<<gl, 256>>>(pw_b, dw_w, g1, b1, m1, v1, g2, b2, m2, v2, out);
}